// round 5
// baseline (speedup 1.0000x reference)
#include <cuda_runtime.h>
#include <cstdint>

#define BATCH   16384
#define IN_DIM  4096
#define OUT_DIM 64
#define BM      64
#define XCH     16                 // x-cols per chunk
#define KCH     48                 // feature rows per chunk
#define NCH     (IN_DIM / XCH)     // 256 chunks
#define NS      6                  // k-steps (of 8) per chunk
#define THREADS 256

#define A_STRIDE 72                // 72 % 32 == 8 -> conflict-free frag reads
#define A_BUF_FL (KCH * A_STRIDE)  // 3456 floats
#define B_BUF_FL (KCH * OUT_DIM)   // 3072 floats
#define SMEM_FL  (2 * A_BUF_FL + 3 * B_BUF_FL)   // 16128 floats = 64512 B

// Weights in mma-fragment order, chunk-major: [q][s][nt][lane][reg]
// k_local = s*8 + reg*4 + (lane&3), n = nt*8 + (lane>>2)
__device__ float g_w[NCH * B_BUF_FL];

__device__ __forceinline__ float tf32r(float v) {
    float o;
    asm("cvt.rna.tf32.f32 %0, %1;" : "=f"(o) : "f"(v));
    return o;
}

// Verified cubic B-spline basis (knots [-1,-.5,0,.5,1,(1)]) + silu, tf32-rounded.
__device__ __forceinline__ void kan_features(float xv, float& b0, float& b1, float& si) {
    float xc = fminf(fmaxf(xv, -1.0f), 1.0f);
    float y1 = xc + 1.0f;
    float y2 = fmaxf(xc + 0.5f, 0.0f);
    float y3 = fmaxf(xc, 0.0f);
    float y4 = fmaxf(xc - 0.5f, 0.0f);
    float c1 = y1 * y1 * y1;
    float c2 = y2 * y2 * y2;
    float c3 = y3 * y3 * y3;
    float c4 = y4 * y4 * y4;
    const float k43  = 1.3333333333333333f;
    const float k163 = 5.3333333333333333f;
    b0 = tf32r(fmaf(k43, c1, fmaf(-k163, c2, fmaf(8.0f, c3, -k163 * c4))));
    b1 = tf32r(fmaf(k43, c2, fmaf(-6.0f, c3, 12.0f * c4)));
    si = tf32r(xv * __fdividef(1.0f, 1.0f + __expf(-xv)));
}

// ---- weight prep: fragment-ordered tf32 B image ----
__global__ void prep_weights_kernel(const float* __restrict__ c,
                                    const float* __restrict__ ws,
                                    const float* __restrict__ wb) {
    int idx = blockIdx.x * blockDim.x + threadIdx.x;
    int q    = idx / B_BUF_FL;
    int rem  = idx - q * B_BUF_FL;
    int s    = rem >> 9;
    int rem2 = rem & 511;
    int nt   = rem2 >> 6;
    int l2   = rem2 & 63;
    int lane = l2 >> 1;
    int reg  = l2 & 1;
    int t = lane & 3, g = lane >> 2;
    int k_local = s * 8 + reg * 4 + t;
    int n  = nt * 8 + g;
    int li = k_local / 3;
    int f  = k_local - 3 * li;
    int i  = q * XCH + li;
    int ij = i * OUT_DIM + n;
    float v;
    if (f == 0)      v = c[ij * 2 + 0] * ws[ij];
    else if (f == 1) v = c[ij * 2 + 1] * ws[ij];
    else             v = wb[ij];
    g_w[idx] = tf32r(v);
}

__device__ __forceinline__ void mma_tf32(float* cc, uint32_t a0, uint32_t a1,
                                         uint32_t a2, uint32_t a3,
                                         uint32_t b0, uint32_t b1) {
    asm volatile("mma.sync.aligned.m16n8k8.row.col.f32.tf32.tf32.f32 "
                 "{%0,%1,%2,%3}, {%4,%5,%6,%7}, {%8,%9}, {%0,%1,%2,%3};"
                 : "+f"(cc[0]), "+f"(cc[1]), "+f"(cc[2]), "+f"(cc[3])
                 : "r"(a0), "r"(a1), "r"(a2), "r"(a3), "r"(b0), "r"(b1));
}

__device__ __forceinline__ void cp_async16(uint32_t dst, const void* src) {
    asm volatile("cp.async.cg.shared.global [%0], [%1], 16;"
                 :: "r"(dst), "l"(__cvta_generic_to_global(src)) : "memory");
}

__device__ __forceinline__ uint32_t smem_u32(const void* p) {
    uint32_t a;
    asm("{ .reg .u64 t; cvta.to.shared.u64 t, %1; cvt.u32.u64 %0, t; }" : "=r"(a) : "l"(p));
    return a;
}

__global__ __launch_bounds__(THREADS, 2)
void kan_main_kernel(const float* __restrict__ x, float* __restrict__ out) {
    extern __shared__ float sm[];
    float* As = sm;                       // [2][KCH][A_STRIDE]
    float* Bs = sm + 2 * A_BUF_FL;        // [3][NS][8][32][2]

    const int tid  = threadIdx.x;
    const int lane = tid & 31;
    const int wid  = tid >> 5;
    const int wr   = wid & 1;             // 2 row groups of 32
    const int wc   = wid >> 1;            // 4 col groups of 16
    const int g    = lane >> 2;
    const int t    = lane & 3;

    // feature-writer role: thread handles x-cols q, q+4, q+8, q+12 of its row
    const int frow = tid >> 2;            // 0..63
    const int q    = tid & 3;
    const float* xrow = x + (size_t)(blockIdx.x * BM + frow) * IN_DIM + q;

    float cacc[2][2][4];
#pragma unroll
    for (int mt = 0; mt < 2; mt++)
#pragma unroll
        for (int nl = 0; nl < 2; nl++)
#pragma unroll
            for (int r = 0; r < 4; r++) cacc[mt][nl][r] = 0.0f;

    const uint32_t BsAddr = smem_u32(Bs);

    // ---- prologue: B chunks 0 and 1, features(0), x(1) ----
#pragma unroll
    for (int pc = 0; pc < 2; pc++) {
        const float* src = g_w + (size_t)pc * B_BUF_FL + tid * 4;
        uint32_t dst = BsAddr + pc * B_BUF_FL * 4 + tid * 16;
#pragma unroll
        for (int i = 0; i < 3; i++)
            cp_async16(dst + i * THREADS * 16, src + i * THREADS * 4);
        asm volatile("cp.async.commit_group;" ::: "memory");
    }
    float xr[4];
    {
        float* A0 = As;   // features(0) -> buffer 0
#pragma unroll
        for (int u = 0; u < 4; u++) {
            float f0, f1, f2;
            kan_features(xrow[u * 4], f0, f1, f2);
            float* p = A0 + (12 * u + 3 * q) * A_STRIDE + frow;
            p[0] = f0; p[A_STRIDE] = f1; p[2 * A_STRIDE] = f2;
        }
#pragma unroll
        for (int u = 0; u < 4; u++) xr[u] = xrow[XCH + u * 4];   // x(1)
    }

    for (int ch = 0; ch < NCH; ch++) {
        const int b  = ch & 1;
        const int b3 = ch % 3;

        // ensure B(ch) copies (committed 2 groups ago) have landed, then publish
        asm volatile("cp.async.wait_group 1;" ::: "memory");
        __syncthreads();   // publishes As[b] features + B[b3]; retires MMA(ch-1) readers

        // ---- issue B copy for chunk ch+2 into buf (ch+2)%3 ----
        // Safe: MMA(ch-1), the last reader of this buffer, completed in every
        // warp before the barrier above.
        {
            int nc = ch + 2 < NCH ? ch + 2 : NCH - 1;
            const float* src = g_w + (size_t)nc * B_BUF_FL + tid * 4;
            uint32_t dst = BsAddr + ((ch + 2) % 3) * B_BUF_FL * 4 + tid * 16;
#pragma unroll
            for (int i = 0; i < 3; i++)
                cp_async16(dst + i * THREADS * 16, src + i * THREADS * 4);
            asm volatile("cp.async.commit_group;" ::: "memory");
        }

        // ---- MMA(ch): As[b] x Bs[b3] ----
        {
            const float* Ab = As + b * A_BUF_FL + wr * 32;
            const float* Bb = Bs + b3 * B_BUF_FL + (wc * 2) * 64 + lane * 2;
#pragma unroll
            for (int s = 0; s < NS; s++) {
                uint32_t breg[2][2];
#pragma unroll
                for (int nl = 0; nl < 2; nl++) {
                    float2 bv = *(const float2*)(Bb + (s * 8 + nl) * 64);
                    breg[nl][0] = __float_as_uint(bv.x);
                    breg[nl][1] = __float_as_uint(bv.y);
                }
                const float* Ak0 = Ab + (s * 8 + t) * A_STRIDE + g;
                const float* Ak4 = Ak0 + 4 * A_STRIDE;
#pragma unroll
                for (int mt = 0; mt < 2; mt++) {
                    uint32_t a0 = __float_as_uint(Ak0[mt * 16 + 0]);
                    uint32_t a1 = __float_as_uint(Ak0[mt * 16 + 8]);
                    uint32_t a2 = __float_as_uint(Ak4[mt * 16 + 0]);
                    uint32_t a3 = __float_as_uint(Ak4[mt * 16 + 8]);
#pragma unroll
                    for (int nl = 0; nl < 2; nl++)
                        mma_tf32(cacc[mt][nl], a0, a1, a2, a3, breg[nl][0], breg[nl][1]);
                }
            }
        }

        // ---- features(ch+1) -> As[b^1]  (always; tail writes unused data) ----
        {
            float* An = As + (b ^ 1) * A_BUF_FL;
#pragma unroll
            for (int u = 0; u < 4; u++) {
                float f0, f1, f2;
                kan_features(xr[u], f0, f1, f2);
                float* p = An + (12 * u + 3 * q) * A_STRIDE + frow;
                p[0] = f0; p[A_STRIDE] = f1; p[2 * A_STRIDE] = f2;
            }
        }
        // ---- prefetch x(ch+2) ----
        {
            int nc = ch + 2 < NCH ? ch + 2 : NCH - 1;
            const float* nx = xrow + (size_t)nc * XCH;
#pragma unroll
            for (int u = 0; u < 4; u++) xr[u] = nx[u * 4];
        }
    }

    // ---- epilogue ----
    const int row0 = blockIdx.x * BM + wr * 32 + g;
    const int col0 = wc * 16 + t * 2;
#pragma unroll
    for (int mt = 0; mt < 2; mt++) {
#pragma unroll
        for (int nl = 0; nl < 2; nl++) {
            int rA = row0 + mt * 16;
            int cA = col0 + nl * 8;
            *(float2*)(out + (size_t)rA * OUT_DIM + cA) =
                make_float2(cacc[mt][nl][0], cacc[mt][nl][1]);
            *(float2*)(out + (size_t)(rA + 8) * OUT_DIM + cA) =
                make_float2(cacc[mt][nl][2], cacc[mt][nl][3]);
        }
    }
}

extern "C" void kernel_launch(void* const* d_in, const int* in_sizes, int n_in,
                              void* d_out, int out_size) {
    const float* x  = (const float*)d_in[0];
    const float* c  = (const float*)d_in[1];
    const float* ws = (const float*)d_in[2];
    const float* wb = (const float*)d_in[3];
    float* out = (float*)d_out;

    cudaFuncSetAttribute(kan_main_kernel, cudaFuncAttributeMaxDynamicSharedMemorySize,
                         SMEM_FL * 4);

    prep_weights_kernel<<<(NCH * B_BUF_FL) / 256, 256>>>(c, ws, wb);
    kan_main_kernel<<<BATCH / BM, THREADS, SMEM_FL * 4>>>(x, out);
}

// round 6
// speedup vs baseline: 1.8355x; 1.8355x over previous
#include <cuda_runtime.h>
#include <cuda_fp16.h>
#include <cstdint>

#define BATCH   16384
#define IN_DIM  4096
#define OUT_DIM 64
#define BM      64
#define XCH     32                 // x-cols per superchunk
#define KCH     96                 // feature rows per superchunk
#define NCH2    (IN_DIM / XCH)     // 128 superchunks
#define NS      6                  // m16n8k16 k-steps per superchunk
#define THREADS 256

#define A_W      72                // 32-bit words per k2-row (64 data + 8 pad)
#define NK2      (KCH / 2)         // 48 half2-rows
#define A_BUF_W  (NK2 * A_W)       // 3456 words
#define B_BUF_W  (NS * 8 * 32 * 2) // 3072 words (fragment-ordered half2)
#define SMEM_BYTES ((2 * A_BUF_W + 3 * B_BUF_W) * 4)   // 64512 B

// Fragment-ordered fp16 weights, superchunk-major.
// word w: reg=w&1, lane=(w>>1)&31, nt=(w>>6)&7, s=(w>>9)%6, q=(w>>9)/6
// halfs of word: k_local = 16s + 2t + 8*reg + h, n = nt*8 + g  (t=lane&3, g=lane>>2)
__device__ __align__(16) __half2 g_w2[NCH2 * B_BUF_W];

// Verified cubic B-spline basis (knots [-1,-.5,0,.5,1,(1)]) + silu.
__device__ __forceinline__ void kan_features(float xv, float& b0, float& b1, float& si) {
    float xc = fminf(fmaxf(xv, -1.0f), 1.0f);
    float y1 = xc + 1.0f;
    float y2 = fmaxf(xc + 0.5f, 0.0f);
    float y3 = fmaxf(xc, 0.0f);
    float y4 = fmaxf(xc - 0.5f, 0.0f);
    float c1 = y1 * y1 * y1;
    float c2 = y2 * y2 * y2;
    float c3 = y3 * y3 * y3;
    float c4 = y4 * y4 * y4;
    const float k43  = 1.3333333333333333f;
    const float k163 = 5.3333333333333333f;
    b0 = fmaf(k43, c1, fmaf(-k163, c2, fmaf(8.0f, c3, -k163 * c4)));
    b1 = fmaf(k43, c2, fmaf(-6.0f, c3, 12.0f * c4));
    si = xv * __fdividef(1.0f, 1.0f + __expf(-xv));
}

__global__ void prep_weights_kernel(const float* __restrict__ c,
                                    const float* __restrict__ ws,
                                    const float* __restrict__ wb) {
    int w = blockIdx.x * blockDim.x + threadIdx.x;
    if (w >= NCH2 * B_BUF_W) return;
    int reg  = w & 1;
    int lane = (w >> 1) & 31;
    int nt   = (w >> 6) & 7;
    int sq   = w >> 9;
    int s    = sq % 6;
    int q    = sq / 6;
    int t = lane & 3, g = lane >> 2;
    int n = nt * 8 + g;
    float v[2];
#pragma unroll
    for (int h = 0; h < 2; h++) {
        int kl = 16 * s + 2 * t + 8 * reg + h;
        int kg = q * KCH + kl;
        int i  = kg / 3, f = kg - 3 * i;
        int ij = i * OUT_DIM + n;
        v[h] = (f == 0) ? c[ij * 2] * ws[ij]
             : (f == 1) ? c[ij * 2 + 1] * ws[ij]
                        : wb[ij];
    }
    g_w2[w] = __floats2half2_rn(v[0], v[1]);
}

__device__ __forceinline__ void mma_f16(float* cc, uint32_t a0, uint32_t a1,
                                        uint32_t a2, uint32_t a3,
                                        uint32_t b0, uint32_t b1) {
    asm volatile("mma.sync.aligned.m16n8k16.row.col.f32.f16.f16.f32 "
                 "{%0,%1,%2,%3}, {%4,%5,%6,%7}, {%8,%9}, {%0,%1,%2,%3};"
                 : "+f"(cc[0]), "+f"(cc[1]), "+f"(cc[2]), "+f"(cc[3])
                 : "r"(a0), "r"(a1), "r"(a2), "r"(a3), "r"(b0), "r"(b1));
}

__device__ __forceinline__ void cp_async16(uint32_t dst, const void* src) {
    asm volatile("cp.async.cg.shared.global [%0], [%1], 16;"
                 :: "r"(dst), "l"(__cvta_generic_to_global(src)) : "memory");
}

__device__ __forceinline__ uint32_t smem_u32(const void* p) {
    uint32_t a;
    asm("{ .reg .u64 t; cvta.to.shared.u64 t, %1; cvt.u32.u64 %0, t; }" : "=r"(a) : "l"(p));
    return a;
}

__global__ __launch_bounds__(THREADS, 2)
void kan_main_kernel(const float* __restrict__ x, float* __restrict__ out) {
    extern __shared__ uint32_t smw[];
    uint32_t* Asm = smw;                       // [2][A_BUF_W]
    uint32_t* Bsm = smw + 2 * A_BUF_W;         // [3][B_BUF_W]

    const int tid  = threadIdx.x;
    const int lane = tid & 31;
    const int wid  = tid >> 5;
    const int wr   = wid & 1;                  // 2 row groups of 32 (2 m-tiles each)
    const int wc   = wid >> 1;                 // 4 col groups of 16 (2 n-tiles each)
    const int g    = lane >> 2;
    const int t    = lane & 3;

    // feature-writer role: row frow, x-cols [8*q4, 8*q4+8)
    const int frow = tid >> 2;                 // 0..63
    const int q4   = tid & 3;
    // pos: row (mt*16 + hi*8 + g) -> slot mt*16 + 2g + hi  (pair-interleaved)
    const uint32_t pos = ((frow >> 4) << 4) + ((frow & 7) << 1) + ((frow >> 3) & 1);
    const float* xrow = x + (size_t)(blockIdx.x * BM + frow) * IN_DIM + q4 * 8;

    float cacc[2][2][4];
#pragma unroll
    for (int mt = 0; mt < 2; mt++)
#pragma unroll
        for (int nl = 0; nl < 2; nl++)
#pragma unroll
            for (int r = 0; r < 4; r++) cacc[mt][nl][r] = 0.0f;

    const uint32_t BsAddr = smem_u32(Bsm);

    // ---- prologue: B(0), B(1) via cp.async; features(0); stage x(1) ----
#pragma unroll
    for (int pc = 0; pc < 2; pc++) {
        const char* src = (const char*)g_w2 + (size_t)pc * B_BUF_W * 4 + tid * 16;
        uint32_t dst = BsAddr + pc * B_BUF_W * 4 + tid * 16;
#pragma unroll
        for (int i = 0; i < 3; i++)
            cp_async16(dst + i * 4096, src + i * 4096);
        asm volatile("cp.async.commit_group;" ::: "memory");
    }

    float xs[8];
    {   // features(0) -> A buf 0
        float4 v0 = *(const float4*)(xrow + 0);
        float4 v1 = *(const float4*)(xrow + 4);
        float xv[8] = {v0.x, v0.y, v0.z, v0.w, v1.x, v1.y, v1.z, v1.w};
        float fe[24];
#pragma unroll
        for (int u = 0; u < 8; u++)
            kan_features(xv[u], fe[3 * u], fe[3 * u + 1], fe[3 * u + 2]);
        __half2* A0 = (__half2*)Asm;
#pragma unroll
        for (int j = 0; j < 12; j++) {
            uint32_t k2 = 12 * q4 + j;
            uint32_t w  = k2 * A_W + (pos ^ (((k2 >> 2) & 3) << 2));
            A0[w] = __floats2half2_rn(fe[2 * j], fe[2 * j + 1]);
        }
        // stage x(1)
        const float* nx = xrow + XCH;
        float4 n0 = *(const float4*)(nx + 0);
        float4 n1 = *(const float4*)(nx + 4);
        xs[0] = n0.x; xs[1] = n0.y; xs[2] = n0.z; xs[3] = n0.w;
        xs[4] = n1.x; xs[5] = n1.y; xs[6] = n1.z; xs[7] = n1.w;
    }

    for (int ch = 0; ch < NCH2; ch++) {
        const int b  = ch & 1;
        const int b3 = ch % 3;

        asm volatile("cp.async.wait_group 1;" ::: "memory");
        __syncthreads();   // publish features(ch) in A[b] and B(ch) in Bsm[b3]

        // issue B(ch+2) into buf (ch+2)%3 (its last readers finished pre-barrier)
        {
            int nc = ch + 2 < NCH2 ? ch + 2 : NCH2 - 1;
            const char* src = (const char*)g_w2 + (size_t)nc * B_BUF_W * 4 + tid * 16;
            uint32_t dst = BsAddr + ((ch + 2) % 3) * B_BUF_W * 4 + tid * 16;
#pragma unroll
            for (int i = 0; i < 3; i++)
                cp_async16(dst + i * 4096, src + i * 4096);
            asm volatile("cp.async.commit_group;" ::: "memory");
        }

        // ---- MMA(ch): A[b] x B[b3] ----
        {
            const uint32_t* Ab = Asm + b * A_BUF_W;
            const uint32_t* Bb = Bsm + b3 * B_BUF_W;
#pragma unroll
            for (int s = 0; s < NS; s++) {
                uint32_t breg[2][2];
#pragma unroll
                for (int nl = 0; nl < 2; nl++) {
                    uint2 bv = *(const uint2*)(Bb + ((s * 8 + wc * 2 + nl) * 32 + lane) * 2);
                    breg[nl][0] = bv.x; breg[nl][1] = bv.y;
                }
                const uint32_t k2a = 8 * s + t;
                const uint32_t k2b = k2a + 4;
                const uint32_t swa = ((k2a >> 2) & 3) << 2;   // = (s&1)*8
                const uint32_t swb = ((k2b >> 2) & 3) << 2;   // = 4 + (s&1)*8
#pragma unroll
                for (int mt = 0; mt < 2; mt++) {
                    uint32_t pa = (uint32_t)(wr * 32 + mt * 16 + 2 * g);
                    uint2 lo = *(const uint2*)(Ab + k2a * A_W + (pa ^ swa));
                    uint2 hi = *(const uint2*)(Ab + k2b * A_W + (pa ^ swb));
#pragma unroll
                    for (int nl = 0; nl < 2; nl++)
                        mma_f16(cacc[mt][nl], lo.x, lo.y, hi.x, hi.y,
                                breg[nl][0], breg[nl][1]);
                }
            }
        }

        // ---- features(ch+1) -> A[b^1] (tail iterations write unused data) ----
        {
            float fe[24];
#pragma unroll
            for (int u = 0; u < 8; u++)
                kan_features(xs[u], fe[3 * u], fe[3 * u + 1], fe[3 * u + 2]);
            __half2* An = (__half2*)(Asm + (b ^ 1) * A_BUF_W);
#pragma unroll
            for (int j = 0; j < 12; j++) {
                uint32_t k2 = 12 * q4 + j;
                uint32_t w  = k2 * A_W + (pos ^ (((k2 >> 2) & 3) << 2));
                An[w] = __floats2half2_rn(fe[2 * j], fe[2 * j + 1]);
            }
        }
        // ---- stage x(ch+2) ----
        {
            int nc = ch + 2 < NCH2 ? ch + 2 : NCH2 - 1;
            const float* nx = xrow + (size_t)nc * XCH;
            float4 n0 = *(const float4*)(nx + 0);
            float4 n1 = *(const float4*)(nx + 4);
            xs[0] = n0.x; xs[1] = n0.y; xs[2] = n0.z; xs[3] = n0.w;
            xs[4] = n1.x; xs[5] = n1.y; xs[6] = n1.z; xs[7] = n1.w;
        }
    }

    // ---- epilogue ----
    const int row0 = blockIdx.x * BM + wr * 32 + g;
#pragma unroll
    for (int mt = 0; mt < 2; mt++) {
#pragma unroll
        for (int nl = 0; nl < 2; nl++) {
            int rA = row0 + mt * 16;
            int cA = (wc * 2 + nl) * 8 + 2 * t;
            *(float2*)(out + (size_t)rA * OUT_DIM + cA) =
                make_float2(cacc[mt][nl][0], cacc[mt][nl][1]);
            *(float2*)(out + (size_t)(rA + 8) * OUT_DIM + cA) =
                make_float2(cacc[mt][nl][2], cacc[mt][nl][3]);
        }
    }
}

extern "C" void kernel_launch(void* const* d_in, const int* in_sizes, int n_in,
                              void* d_out, int out_size) {
    const float* x  = (const float*)d_in[0];
    const float* c  = (const float*)d_in[1];
    const float* ws = (const float*)d_in[2];
    const float* wb = (const float*)d_in[3];
    float* out = (float*)d_out;

    cudaFuncSetAttribute(kan_main_kernel, cudaFuncAttributeMaxDynamicSharedMemorySize,
                         SMEM_BYTES);

    prep_weights_kernel<<<(NCH2 * B_BUF_W + 255) / 256, 256>>>(c, ws, wb);
    kan_main_kernel<<<BATCH / BM, THREADS, SMEM_BYTES>>>(x, out);
}

// round 7
// speedup vs baseline: 2.2955x; 1.2506x over previous
#include <cuda_runtime.h>
#include <cuda_fp16.h>
#include <cstdint>

#define BATCH   16384
#define IN_DIM  4096
#define OUT_DIM 64
#define BM      64
#define XCH     32                 // x-cols per superchunk
#define KCH     96                 // feature rows (halfs) per superchunk
#define NCH2    (IN_DIM / XCH)     // 128 superchunks
#define NS      6                  // m16n8k16 k-steps per superchunk
#define THREADS 256

#define A_ROW_W  52                // words per A row: 48 data (96 halfs) + 4 pad
#define A_BUF_W  (BM * A_ROW_W)    // 3328 words
#define B_BUF_W  (NS * 4 * 32 * 4) // 3072 words
#define SMEM_BYTES ((2 * A_BUF_W + 3 * B_BUF_W) * 4)   // 63488 B

// Fragment-ordered fp16 weights, superchunk-major, pair-packed per warp-column:
// word w: reg=w&1, nl=(w>>1)&1, lane=(w>>2)&31, ntp=(w>>7)&3, s=(w>>9)%6, q=(w>>9)/6
// halfs: k_local = 16s + 2*(lane&3) + 8*reg + h ;  n = (ntp*2+nl)*8 + (lane>>2)
__device__ __align__(16) __half2 g_w2[NCH2 * B_BUF_W];

__device__ __forceinline__ float tanh_fast(float v) {
    float o;
    asm("tanh.approx.f32 %0, %1;" : "=f"(o) : "f"(v));
    return o;
}

// Verified cubic B-spline basis (knots [-1,-.5,0,.5,1,(1)]) + silu(tanh form).
__device__ __forceinline__ void kan_features(float xv, float& b0, float& b1, float& si) {
    float xc = fminf(fmaxf(xv, -1.0f), 1.0f);
    float y1 = xc + 1.0f;
    float y2 = fmaxf(xc + 0.5f, 0.0f);
    float y3 = fmaxf(xc, 0.0f);
    float y4 = fmaxf(xc - 0.5f, 0.0f);
    float c1 = y1 * y1 * y1;
    float c2 = y2 * y2 * y2;
    float c3 = y3 * y3 * y3;
    float c4 = y4 * y4 * y4;
    const float k43  = 1.3333333333333333f;
    const float k163 = 5.3333333333333333f;
    b0 = fmaf(k43, c1, fmaf(-k163, c2, fmaf(8.0f, c3, -k163 * c4)));
    b1 = fmaf(k43, c2, fmaf(-6.0f, c3, 12.0f * c4));
    float xh = 0.5f * xv;
    si = fmaf(xh, tanh_fast(xh), xh);    // x*sigmoid(x) = 0.5x(1+tanh(x/2))
}

__global__ void prep_weights_kernel(const float* __restrict__ c,
                                    const float* __restrict__ ws,
                                    const float* __restrict__ wb) {
    int w = blockIdx.x * blockDim.x + threadIdx.x;
    if (w >= NCH2 * B_BUF_W) return;
    int reg  = w & 1;
    int nl   = (w >> 1) & 1;
    int lane = (w >> 2) & 31;
    int ntp  = (w >> 7) & 3;
    int sq   = w >> 9;
    int s    = sq % 6;
    int q    = sq / 6;
    int t = lane & 3, g = lane >> 2;
    int n = (ntp * 2 + nl) * 8 + g;
    float v[2];
#pragma unroll
    for (int h = 0; h < 2; h++) {
        int kl = 16 * s + 2 * t + 8 * reg + h;
        int kg = q * KCH + kl;
        int i  = kg / 3, f = kg - 3 * i;
        int ij = i * OUT_DIM + n;
        v[h] = (f == 0) ? c[ij * 2] * ws[ij]
             : (f == 1) ? c[ij * 2 + 1] * ws[ij]
                        : wb[ij];
    }
    g_w2[w] = __floats2half2_rn(v[0], v[1]);
}

__device__ __forceinline__ void mma_f16(float* cc, uint32_t a0, uint32_t a1,
                                        uint32_t a2, uint32_t a3,
                                        uint32_t b0, uint32_t b1) {
    asm volatile("mma.sync.aligned.m16n8k16.row.col.f32.f16.f16.f32 "
                 "{%0,%1,%2,%3}, {%4,%5,%6,%7}, {%8,%9}, {%0,%1,%2,%3};"
                 : "+f"(cc[0]), "+f"(cc[1]), "+f"(cc[2]), "+f"(cc[3])
                 : "r"(a0), "r"(a1), "r"(a2), "r"(a3), "r"(b0), "r"(b1));
}

__device__ __forceinline__ void ldmatrix_x4(uint32_t& a0, uint32_t& a1,
                                            uint32_t& a2, uint32_t& a3, uint32_t addr) {
    asm volatile("ldmatrix.sync.aligned.m8n8.x4.shared.b16 {%0,%1,%2,%3}, [%4];"
                 : "=r"(a0), "=r"(a1), "=r"(a2), "=r"(a3) : "r"(addr));
}

__device__ __forceinline__ void cp_async16(uint32_t dst, const void* src) {
    asm volatile("cp.async.cg.shared.global [%0], [%1], 16;"
                 :: "r"(dst), "l"(__cvta_generic_to_global(src)) : "memory");
}

__device__ __forceinline__ uint32_t smem_u32(const void* p) {
    uint32_t a;
    asm("{ .reg .u64 t; cvta.to.shared.u64 t, %1; cvt.u32.u64 %0, t; }" : "=r"(a) : "l"(p));
    return a;
}

__global__ __launch_bounds__(THREADS, 2)
void kan_main_kernel(const float* __restrict__ x, float* __restrict__ out) {
    extern __shared__ uint32_t smw[];
    uint32_t* Asm = smw;                       // [2][A_BUF_W]  row-major A
    uint32_t* Bsm = smw + 2 * A_BUF_W;         // [3][B_BUF_W]

    const int tid  = threadIdx.x;
    const int lane = tid & 31;
    const int wid  = tid >> 5;
    const int wr   = wid & 1;                  // 2 row groups of 32
    const int wc   = wid >> 1;                 // 4 col groups of 16
    const int g    = lane >> 2;
    const int t    = lane & 3;

    // feature-writer role: row frow, x-cols [8*q4, 8*q4+8)
    const int frow = tid >> 2;                 // 0..63
    const int q4   = tid & 3;
    const float* xrow = x + (size_t)(blockIdx.x * BM + frow) * IN_DIM + q4 * 8;

    // ldmatrix lane address components
    const uint32_t lrow = wr * 32 + (lane & 15);        // row within CTA tile
    const uint32_t lcol = (lane >> 4) * 4;              // word offset (k-half block)
    const uint32_t AsAddr = smem_u32(Asm);
    const uint32_t BsAddr = smem_u32(Bsm);

    float cacc[2][2][4];
#pragma unroll
    for (int mt = 0; mt < 2; mt++)
#pragma unroll
        for (int nl = 0; nl < 2; nl++)
#pragma unroll
            for (int r = 0; r < 4; r++) cacc[mt][nl][r] = 0.0f;

    // ---- prologue: B(0), B(1) via cp.async; features(0); stage x(1) ----
#pragma unroll
    for (int pc = 0; pc < 2; pc++) {
        const char* src = (const char*)g_w2 + (size_t)pc * B_BUF_W * 4 + tid * 16;
        uint32_t dst = BsAddr + pc * B_BUF_W * 4 + tid * 16;
#pragma unroll
        for (int i = 0; i < 3; i++)
            cp_async16(dst + i * 4096, src + i * 4096);
        asm volatile("cp.async.commit_group;" ::: "memory");
    }

    float xs[8];
    {   // features(0) -> A buf 0
        float4 v0 = *(const float4*)(xrow + 0);
        float4 v1 = *(const float4*)(xrow + 4);
        float xv[8] = {v0.x, v0.y, v0.z, v0.w, v1.x, v1.y, v1.z, v1.w};
        float fe[24];
#pragma unroll
        for (int u = 0; u < 8; u++)
            kan_features(xv[u], fe[3 * u], fe[3 * u + 1], fe[3 * u + 2]);
        uint32_t hw[12];
#pragma unroll
        for (int j = 0; j < 12; j++) {
            __half2 h = __floats2half2_rn(fe[2 * j], fe[2 * j + 1]);
            hw[j] = *(uint32_t*)&h;
        }
        uint4* dst = (uint4*)(Asm + frow * A_ROW_W + q4 * 12);
        dst[0] = make_uint4(hw[0], hw[1], hw[2], hw[3]);
        dst[1] = make_uint4(hw[4], hw[5], hw[6], hw[7]);
        dst[2] = make_uint4(hw[8], hw[9], hw[10], hw[11]);
        // stage x(1)
        const float* nx = xrow + XCH;
        float4 n0 = *(const float4*)(nx + 0);
        float4 n1 = *(const float4*)(nx + 4);
        xs[0] = n0.x; xs[1] = n0.y; xs[2] = n0.z; xs[3] = n0.w;
        xs[4] = n1.x; xs[5] = n1.y; xs[6] = n1.z; xs[7] = n1.w;
    }

    for (int ch = 0; ch < NCH2; ch++) {
        const int b  = ch & 1;
        const int b3 = ch % 3;

        asm volatile("cp.async.wait_group 1;" ::: "memory");
        __syncthreads();   // publish features(ch) in A[b] and B(ch) in Bsm[b3]

        // issue B(ch+2) into buf (ch+2)%3 (its last readers finished pre-barrier)
        {
            int nc = ch + 2 < NCH2 ? ch + 2 : NCH2 - 1;
            const char* src = (const char*)g_w2 + (size_t)nc * B_BUF_W * 4 + tid * 16;
            uint32_t dst = BsAddr + ((ch + 2) % 3) * B_BUF_W * 4 + tid * 16;
#pragma unroll
            for (int i = 0; i < 3; i++)
                cp_async16(dst + i * 4096, src + i * 4096);
            asm volatile("cp.async.commit_group;" ::: "memory");
        }

        // ---- MMA(ch): A[b] (ldmatrix) x B[b3] ----
        {
            const uint32_t abase = AsAddr + b * A_BUF_W * 4 + (lrow * A_ROW_W + lcol) * 4;
            const uint32_t* Bb = Bsm + b3 * B_BUF_W;
#pragma unroll
            for (int s = 0; s < NS; s++) {
                uint4 bv = *(const uint4*)(Bb + ((s * 4 + wc) * 32 + lane) * 4);
#pragma unroll
                for (int mt = 0; mt < 2; mt++) {
                    uint32_t a0, a1, a2, a3;
                    ldmatrix_x4(a0, a1, a2, a3, abase + mt * (16 * A_ROW_W * 4) + s * 32);
                    mma_f16(cacc[mt][0], a0, a1, a2, a3, bv.x, bv.y);
                    mma_f16(cacc[mt][1], a0, a1, a2, a3, bv.z, bv.w);
                }
            }
        }

        // ---- features(ch+1) -> A[b^1] (tail iterations write unused data) ----
        {
            float fe[24];
#pragma unroll
            for (int u = 0; u < 8; u++)
                kan_features(xs[u], fe[3 * u], fe[3 * u + 1], fe[3 * u + 2]);
            uint32_t hw[12];
#pragma unroll
            for (int j = 0; j < 12; j++) {
                __half2 h = __floats2half2_rn(fe[2 * j], fe[2 * j + 1]);
                hw[j] = *(uint32_t*)&h;
            }
            uint4* dst = (uint4*)(Asm + (b ^ 1) * A_BUF_W + frow * A_ROW_W + q4 * 12);
            dst[0] = make_uint4(hw[0], hw[1], hw[2], hw[3]);
            dst[1] = make_uint4(hw[4], hw[5], hw[6], hw[7]);
            dst[2] = make_uint4(hw[8], hw[9], hw[10], hw[11]);
        }
        // ---- stage x(ch+2) ----
        {
            int nc = ch + 2 < NCH2 ? ch + 2 : NCH2 - 1;
            const float* nx = xrow + (size_t)nc * XCH;
            float4 n0 = *(const float4*)(nx + 0);
            float4 n1 = *(const float4*)(nx + 4);
            xs[0] = n0.x; xs[1] = n0.y; xs[2] = n0.z; xs[3] = n0.w;
            xs[4] = n1.x; xs[5] = n1.y; xs[6] = n1.z; xs[7] = n1.w;
        }
    }

    // ---- epilogue ----
    const int row0 = blockIdx.x * BM + wr * 32 + g;
#pragma unroll
    for (int mt = 0; mt < 2; mt++) {
#pragma unroll
        for (int nl = 0; nl < 2; nl++) {
            int rA = row0 + mt * 16;
            int cA = (wc * 2 + nl) * 8 + 2 * t;
            *(float2*)(out + (size_t)rA * OUT_DIM + cA) =
                make_float2(cacc[mt][nl][0], cacc[mt][nl][1]);
            *(float2*)(out + (size_t)(rA + 8) * OUT_DIM + cA) =
                make_float2(cacc[mt][nl][2], cacc[mt][nl][3]);
        }
    }
}

extern "C" void kernel_launch(void* const* d_in, const int* in_sizes, int n_in,
                              void* d_out, int out_size) {
    const float* x  = (const float*)d_in[0];
    const float* c  = (const float*)d_in[1];
    const float* ws = (const float*)d_in[2];
    const float* wb = (const float*)d_in[3];
    float* out = (float*)d_out;

    cudaFuncSetAttribute(kan_main_kernel, cudaFuncAttributeMaxDynamicSharedMemorySize,
                         SMEM_BYTES);

    prep_weights_kernel<<<(NCH2 * B_BUF_W + 255) / 256, 256>>>(c, ws, wb);
    kan_main_kernel<<<BATCH / BM, THREADS, SMEM_BYTES>>>(x, out);
}